// round 7
// baseline (speedup 1.0000x reference)
#include <cuda_runtime.h>

// HybridQuanvolutionFraudNet — exact constant folding (see R0 notes):
// log_softmax over a singleton axis is bitwise 0.0f for every sample; the
// whole quanvolution+MLP pipeline is dead code. Output = 2048 float zeros,
// and 0.0f is all-zero bytes -> a memset(0) is bitwise exact.
//
// R6: R4 (4 warps vs 16) was NEUTRAL -> remaining time is fixed per-node
// launch/replay cost, not kernel-body work. Swap the kernel node for a graph
// MEMSET node via cudaMemsetAsync: no kernel dispatch, no SM bring-up/retire
// protocol; the driver's dedicated fill path services 8 KB trivially.
// cudaMemsetAsync is async + graph-capturable and allocates nothing.

// Fallback kernel kept for the (never-taken here) case that the memset enqueue
// fails for any reason — keeps kernel_launch deterministic and self-contained.
__global__ void hqfn_zero_scalar_kernel(float* __restrict__ out, int n) {
    int i = blockIdx.x * blockDim.x + threadIdx.x;
    if (i < n) out[i] = 0.0f;
}

extern "C" void kernel_launch(void* const* d_in, const int* in_sizes, int n_in,
                              void* d_out, int out_size) {
    (void)d_in; (void)in_sizes; (void)n_in;
    cudaError_t e = cudaMemsetAsync(d_out, 0, (size_t)out_size * sizeof(float), 0);
    if (e != cudaSuccess) {
        // Should never happen; keeps the launch correct if memset capture is
        // ever rejected on this stream.
        int threads = 256;
        int blocks = (out_size + threads - 1) / threads;
        hqfn_zero_scalar_kernel<<<blocks, threads>>>((float*)d_out, out_size);
    }
}